// round 12
// baseline (speedup 1.0000x reference)
#include <cuda_runtime.h>
#include <cuda_fp16.h>
#include <cstdint>

using fp16 = __half;

constexpr int KDIM = 4096;
constexpr size_t SZ_W = (size_t)4096 * 4096;
constexpr size_t SZ_X = (size_t)8192 * 4096;

// ---------------- static device scratch (all single fp16) ----------------
__device__ fp16 g_Ut[SZ_W];       // Ut[o,a] = U[a,o]
__device__ fp16 g_Vt[SZ_W];       // Vt[i,b] = V[b,i]
__device__ fp16 g_qf[SZ_W];       // q[b,a] as fp16 (exact)
__device__ fp16 g_x[SZ_X];        // x[m,i]
__device__ fp16 g_T1[SZ_W];       // T[o,b]
__device__ fp16 g_W[SZ_W];        // Wtt[o,i]
__device__ float g_cs_part[8 * 4096];   // partial colsums of U

// ---------------- PTX helpers ----------------
__device__ __forceinline__ uint32_t smem_u32(const void* p) {
    uint32_t a;
    asm("{ .reg .u64 t; cvta.to.shared.u64 t, %1; cvt.u32.u64 %0, t; }" : "=r"(a) : "l"(p));
    return a;
}
__device__ __forceinline__ void cp16(uint32_t dst, const void* src) {
    asm volatile("cp.async.cg.shared.global [%0], [%1], 16;" :: "r"(dst), "l"(src));
}
__device__ __forceinline__ void ldsm4(uint32_t* r, uint32_t addr) {
    asm volatile("ldmatrix.sync.aligned.m8n8.x4.shared.b16 {%0,%1,%2,%3}, [%4];"
                 : "=r"(r[0]), "=r"(r[1]), "=r"(r[2]), "=r"(r[3]) : "r"(addr));
}
__device__ __forceinline__ void mma16816(float* c, const uint32_t* a, const uint32_t* b) {
    asm volatile("mma.sync.aligned.m16n8k16.row.col.f32.f16.f16.f32 "
                 "{%0,%1,%2,%3}, {%4,%5,%6,%7}, {%8,%9}, {%0,%1,%2,%3};"
                 : "+f"(c[0]), "+f"(c[1]), "+f"(c[2]), "+f"(c[3])
                 : "r"(a[0]), "r"(a[1]), "r"(a[2]), "r"(a[3]), "r"(b[0]), "r"(b[1]));
}
__device__ __forceinline__ uint32_t sw128(uint32_t o) { return o ^ ((o >> 3) & 0x70); }

// ---------------- preprocessing ----------------
template <int WHICH>   // 0: U -> g_Ut (transposed). 1: V -> g_Vt (transposed).
__global__ void transconv(const float* __restrict__ src) {
    __shared__ float t[32][33];
    int c0 = blockIdx.x * 32, r0 = blockIdx.y * 32;
    int tx = threadIdx.x, ty = threadIdx.y;
#pragma unroll
    for (int j = 0; j < 4; j++)
        t[ty + j * 8][tx] = src[(size_t)(r0 + ty + j * 8) * 4096 + c0 + tx];
    __syncthreads();
#pragma unroll
    for (int j = 0; j < 4; j++) {
        int c = c0 + ty + j * 8;
        float v = t[tx][ty + j * 8];
        fp16* dst = (WHICH == 0) ? g_Ut : g_Vt;
        dst[(size_t)c * 4096 + r0 + tx] = __float2half_rn(v);
    }
}

__global__ void convx(const float* __restrict__ xin) {
    size_t i = (size_t)blockIdx.x * 256 + threadIdx.x;
    float4 v = ((const float4*)xin)[i];
    union { fp16 b[4]; uint2 u; } H;
    H.b[0] = __float2half_rn(v.x);
    H.b[1] = __float2half_rn(v.y);
    H.b[2] = __float2half_rn(v.z);
    H.b[3] = __float2half_rn(v.w);
    ((uint2*)g_x)[i] = H.u;
}

__global__ void convq(const int* __restrict__ q) {
    size_t i = (size_t)blockIdx.x * 256 + threadIdx.x;
    int4 v = ((const int4*)q)[i];
    union { fp16 b[4]; uint2 u; } H;
    H.b[0] = __float2half_rn((float)v.x);
    H.b[1] = __float2half_rn((float)v.y);
    H.b[2] = __float2half_rn((float)v.z);
    H.b[3] = __float2half_rn((float)v.w);
    ((uint2*)g_qf)[i] = H.u;
}

__global__ void colsum_part(const float* __restrict__ U) {
    int col = blockIdx.x * 256 + threadIdx.x;
    int seg = blockIdx.y;
    float s = 0.f;
    for (int k = seg * 512; k < seg * 512 + 512; k++)
        s += U[(size_t)k * 4096 + col];
    g_cs_part[seg * 4096 + col] = s;
}

// ---------------- HMMA GEMM (fp16 m16n8k16, fp32 accum, single x single) ----------------
// C[M,N] = sum_k A[m,k]*B[n,k] (both K-major). ONE pass per GEMM.
// MODE 0: A=Ut, B=q.   epi: v*dq_mul - dq_sub*colsum[row] -> T1 (fp16)
// MODE 1: A=T1, B=Vt.  epi: v / scaleWH[col]              -> W  (fp16)
// MODE 2: A=x,  B=W.   epi: v + bias[col]                 -> out (fp32)
// Pipeline: 2-stage BK=64 (proven best) + NEW register-level fragment double-buffer.
constexpr int BM = 128, BN = 256, BK = 64, NCHUNK = KDIM / BK;
constexpr uint32_t TILE_A = 128 * 128;   // 16 KB
constexpr uint32_t TILE_B = 256 * 128;   // 32 KB
constexpr uint32_t OFF_A = 0, OFF_B = TILE_A;
constexpr uint32_t ST = TILE_A + TILE_B;           // 48 KB per stage
constexpr uint32_t SMEM_SZ = 2 * ST + 1024;        // 97 KB
constexpr int WM = 64, WN = 64, MT = WM / 16, NT = WN / 8;

template <int MODE>
__global__ __launch_bounds__(256, 1) void hgemm(const float* __restrict__ aux,
                                                float* __restrict__ outp) {
    const fp16 *A, *B;
    if (MODE == 0) { A = g_Ut; B = g_qf; }
    if (MODE == 1) { A = g_T1; B = g_Vt; }
    if (MODE == 2) { A = g_x;  B = g_W; }

    extern __shared__ char dsm[];
    const uint32_t sbase = (smem_u32(dsm) + 1023u) & ~1023u;

    const int tid = threadIdx.x;
    const int wid = tid >> 5, lane = tid & 31;
    const int warp_m = wid >> 2;   // 0..1
    const int warp_n = wid & 3;    // 0..3
    const int m0 = blockIdx.y * BM, n0 = blockIdx.x * BN;

    float acc[MT][NT][4];
#pragma unroll
    for (int a = 0; a < MT; a++)
#pragma unroll
        for (int b = 0; b < NT; b++)
#pragma unroll
            for (int d = 0; d < 4; d++) acc[a][b][d] = 0.f;

    auto load_stage = [&](int s, int c) {
        const uint32_t sb = sbase + (uint32_t)s * ST;
        const int k0 = c * BK;
#pragma unroll
        for (int t = 0; t < 4; t++) {          // A: 1024 slots
            int idx = tid + t * 256;
            int r = idx >> 3, cc = idx & 7;
            uint32_t sw = sw128((uint32_t)(r * 128 + cc * 16));
            cp16(sb + OFF_A + sw, A + (size_t)(m0 + r) * KDIM + k0 + cc * 8);
        }
#pragma unroll
        for (int t = 0; t < 8; t++) {          // B: 2048 slots
            int idx = tid + t * 256;
            int r = idx >> 3, cc = idx & 7;
            uint32_t sw = sw128((uint32_t)(r * 128 + cc * 16));
            cp16(sb + OFF_B + sw, B + (size_t)(n0 + r) * KDIM + k0 + cc * 8);
        }
        asm volatile("cp.async.commit_group;");
    };

    load_stage(0, 0);

    const uint32_t a_row = (uint32_t)(warp_m * WM + (lane & 15));
    const uint32_t a_kb  = (uint32_t)((lane >> 4) << 4);
    const uint32_t b_row = (uint32_t)(warp_n * WN + ((lane >> 4) << 3) + (lane & 7));
    const uint32_t b_kb  = (uint32_t)(((lane >> 3) & 1) << 4);

    // double-buffered fragments: [buf][...]
    uint32_t ar[2][MT][4], br[2][NT][2];

    auto load_frags = [&](int buf, uint32_t sb, int ks) {
#pragma unroll
        for (int mt = 0; mt < MT; mt++) {
            uint32_t o = sw128((a_row + mt * 16) * 128 + ks * 32 + a_kb);
            ldsm4(ar[buf][mt], sb + OFF_A + o);
        }
#pragma unroll
        for (int np = 0; np < NT / 2; np++) {
            uint32_t o = sw128((b_row + np * 16) * 128 + ks * 32 + b_kb);
            uint32_t tmp[4];
            ldsm4(tmp, sb + OFF_B + o);
            br[buf][2 * np][0] = tmp[0]; br[buf][2 * np][1] = tmp[1];
            br[buf][2 * np + 1][0] = tmp[2]; br[buf][2 * np + 1][1] = tmp[3];
        }
    };

    for (int c = 0; c < NCHUNK; c++) {
        asm volatile("cp.async.wait_group 0;");
        __syncthreads();
        if (c + 1 < NCHUNK) load_stage((c + 1) & 1, c + 1);

        const uint32_t sb = sbase + (uint32_t)(c & 1) * ST;
        load_frags(0, sb, 0);
#pragma unroll
        for (int ks = 0; ks < BK / 16; ks++) {
            const int cur = ks & 1, nxt = cur ^ 1;
            if (ks + 1 < BK / 16) load_frags(nxt, sb, ks + 1);
#pragma unroll
            for (int mt = 0; mt < MT; mt++)
#pragma unroll
                for (int nt = 0; nt < NT; nt++)
                    mma16816(acc[mt][nt], ar[cur][mt], br[cur][nt]);
        }
    }

    // ---------------- epilogue ----------------
    const int gid = lane >> 2, tig = lane & 3;
    float dq_mul = 0.f, dq_sub = 0.f;
    if (MODE == 0) { float sc = aux[0]; dq_mul = sc * (2.0f / 15.0f); dq_sub = sc; }

    float c0f[NT], c1f[NT];
#pragma unroll
    for (int nt = 0; nt < NT; nt++) {
        int col = n0 + warp_n * WN + nt * 8 + tig * 2;
        if (MODE == 1) { c0f[nt] = 1.0f / aux[col]; c1f[nt] = 1.0f / aux[col + 1]; }
        else if (MODE == 2) { c0f[nt] = aux[col]; c1f[nt] = aux[col + 1]; }
        else { c0f[nt] = 0.f; c1f[nt] = 0.f; }
    }

#pragma unroll
    for (int mt = 0; mt < MT; mt++) {
        int r0 = m0 + warp_m * WM + mt * 16 + gid;
        int r1 = r0 + 8;
        float sub0 = 0.f, sub1 = 0.f;
        if (MODE == 0) {
            float cs0 = 0.f, cs1 = 0.f;
#pragma unroll
            for (int p = 0; p < 8; p++) {
                cs0 += g_cs_part[p * 4096 + r0];
                cs1 += g_cs_part[p * 4096 + r1];
            }
            sub0 = dq_sub * cs0; sub1 = dq_sub * cs1;
        }
#pragma unroll
        for (int nt = 0; nt < NT; nt++) {
            int col = n0 + warp_n * WN + nt * 8 + tig * 2;
            float v0 = acc[mt][nt][0], v1 = acc[mt][nt][1];
            float v2 = acc[mt][nt][2], v3 = acc[mt][nt][3];
            if (MODE == 0) {
                v0 = v0 * dq_mul - sub0; v1 = v1 * dq_mul - sub0;
                v2 = v2 * dq_mul - sub1; v3 = v3 * dq_mul - sub1;
            } else if (MODE == 1) {
                v0 *= c0f[nt]; v1 *= c1f[nt]; v2 *= c0f[nt]; v3 *= c1f[nt];
            } else {
                v0 += c0f[nt]; v1 += c1f[nt]; v2 += c0f[nt]; v3 += c1f[nt];
            }
            if (MODE == 2) {
                *(float2*)(outp + (size_t)r0 * 4096 + col) = make_float2(v0, v1);
                *(float2*)(outp + (size_t)r1 * 4096 + col) = make_float2(v2, v3);
            } else {
                fp16* C = (MODE == 0) ? g_T1 : g_W;
                union { fp16 b[2]; uint32_t u; } h;
                h.b[0] = __float2half_rn(v0); h.b[1] = __float2half_rn(v1);
                *(uint32_t*)(C + (size_t)r0 * 4096 + col) = h.u;
                h.b[0] = __float2half_rn(v2); h.b[1] = __float2half_rn(v3);
                *(uint32_t*)(C + (size_t)r1 * 4096 + col) = h.u;
            }
        }
    }
}

// ---------------- host ----------------
extern "C" void kernel_launch(void* const* d_in, const int* in_sizes, int n_in,
                              void* d_out, int out_size) {
    const float* x       = (const float*)d_in[0];
    const int*   qweight = (const int*)  d_in[1];
    const float* scale   = (const float*)d_in[2];
    const float* scaleWH = (const float*)d_in[3];
    const float* bias    = (const float*)d_in[4];
    const float* U       = (const float*)d_in[5];
    const float* V       = (const float*)d_in[6];
    float*       out     = (float*)d_out;

    cudaFuncSetAttribute(hgemm<0>, cudaFuncAttributeMaxDynamicSharedMemorySize, SMEM_SZ);
    cudaFuncSetAttribute(hgemm<1>, cudaFuncAttributeMaxDynamicSharedMemorySize, SMEM_SZ);
    cudaFuncSetAttribute(hgemm<2>, cudaFuncAttributeMaxDynamicSharedMemorySize, SMEM_SZ);

    dim3 tb32(32, 8);
    colsum_part<<<dim3(16, 8), 256>>>(U);                         // 0
    transconv<0><<<dim3(128, 128), tb32>>>(U);                    // 1
    convq<<<16384, 256>>>(qweight);                               // 2
    hgemm<0><<<dim3(16, 32), 256, SMEM_SZ>>>(scale, nullptr);     // 3 <- profiled
    transconv<1><<<dim3(128, 128), tb32>>>(V);                    // 4
    hgemm<1><<<dim3(16, 32), 256, SMEM_SZ>>>(scaleWH, nullptr);   // 5
    convx<<<(unsigned)(SZ_X / 4 / 256), 256>>>(x);                // 6
    hgemm<2><<<dim3(16, 64), 256, SMEM_SZ>>>(bias, out);          // 7
}

// round 13
// speedup vs baseline: 1.1097x; 1.1097x over previous
#include <cuda_runtime.h>
#include <cuda_fp16.h>
#include <cstdint>

using fp16 = __half;

constexpr int KDIM = 4096;
constexpr size_t SZ_W = (size_t)4096 * 4096;
constexpr size_t SZ_X = (size_t)8192 * 4096;

// ---------------- static device scratch (all single fp16) ----------------
__device__ fp16 g_Ut[SZ_W];       // Ut[o,a] = U[a,o]
__device__ fp16 g_Vt[SZ_W];       // Vt[i,b] = V[b,i]
__device__ fp16 g_qf[SZ_W];       // q[b,a] as fp16 (exact)
__device__ fp16 g_x[SZ_X];        // x[m,i]
__device__ fp16 g_T1[SZ_W];       // T[o,b]
__device__ fp16 g_W[SZ_W];        // Wtt[o,i]
__device__ float g_cs_part[8 * 4096];   // partial colsums of U

// ---------------- PTX helpers ----------------
__device__ __forceinline__ uint32_t smem_u32(const void* p) {
    uint32_t a;
    asm("{ .reg .u64 t; cvta.to.shared.u64 t, %1; cvt.u32.u64 %0, t; }" : "=r"(a) : "l"(p));
    return a;
}
__device__ __forceinline__ void cp16(uint32_t dst, const void* src) {
    asm volatile("cp.async.cg.shared.global [%0], [%1], 16;" :: "r"(dst), "l"(src));
}
__device__ __forceinline__ void ldsm4(uint32_t* r, uint32_t addr) {
    asm volatile("ldmatrix.sync.aligned.m8n8.x4.shared.b16 {%0,%1,%2,%3}, [%4];"
                 : "=r"(r[0]), "=r"(r[1]), "=r"(r[2]), "=r"(r[3]) : "r"(addr));
}
__device__ __forceinline__ void mma16816(float* c, const uint32_t* a, const uint32_t* b) {
    asm volatile("mma.sync.aligned.m16n8k16.row.col.f32.f16.f16.f32 "
                 "{%0,%1,%2,%3}, {%4,%5,%6,%7}, {%8,%9}, {%0,%1,%2,%3};"
                 : "+f"(c[0]), "+f"(c[1]), "+f"(c[2]), "+f"(c[3])
                 : "r"(a[0]), "r"(a[1]), "r"(a[2]), "r"(a[3]), "r"(b[0]), "r"(b[1]));
}
__device__ __forceinline__ uint32_t sw128(uint32_t o) { return o ^ ((o >> 3) & 0x70); }

// ---------------- preprocessing ----------------
template <int WHICH>   // 0: U -> g_Ut (transposed). 1: V -> g_Vt (transposed).
__global__ void transconv(const float* __restrict__ src) {
    __shared__ float t[32][33];
    int c0 = blockIdx.x * 32, r0 = blockIdx.y * 32;
    int tx = threadIdx.x, ty = threadIdx.y;
#pragma unroll
    for (int j = 0; j < 4; j++)
        t[ty + j * 8][tx] = src[(size_t)(r0 + ty + j * 8) * 4096 + c0 + tx];
    __syncthreads();
#pragma unroll
    for (int j = 0; j < 4; j++) {
        int c = c0 + ty + j * 8;
        float v = t[tx][ty + j * 8];
        fp16* dst = (WHICH == 0) ? g_Ut : g_Vt;
        dst[(size_t)c * 4096 + r0 + tx] = __float2half_rn(v);
    }
}

__global__ void convx(const float* __restrict__ xin) {
    size_t i = (size_t)blockIdx.x * 256 + threadIdx.x;
    float4 v = ((const float4*)xin)[i];
    union { fp16 b[4]; uint2 u; } H;
    H.b[0] = __float2half_rn(v.x);
    H.b[1] = __float2half_rn(v.y);
    H.b[2] = __float2half_rn(v.z);
    H.b[3] = __float2half_rn(v.w);
    ((uint2*)g_x)[i] = H.u;
}

__global__ void convq(const int* __restrict__ q) {
    size_t i = (size_t)blockIdx.x * 256 + threadIdx.x;
    int4 v = ((const int4*)q)[i];
    union { fp16 b[4]; uint2 u; } H;
    H.b[0] = __float2half_rn((float)v.x);
    H.b[1] = __float2half_rn((float)v.y);
    H.b[2] = __float2half_rn((float)v.z);
    H.b[3] = __float2half_rn((float)v.w);
    ((uint2*)g_qf)[i] = H.u;
}

__global__ void colsum_part(const float* __restrict__ U) {
    int col = blockIdx.x * 256 + threadIdx.x;
    int seg = blockIdx.y;
    float s = 0.f;
    for (int k = seg * 512; k < seg * 512 + 512; k++)
        s += U[(size_t)k * 4096 + col];
    g_cs_part[seg * 4096 + col] = s;
}

// ---------------- HMMA GEMM (fp16 m16n8k16, fp32 accum, single x single) ----------------
// C[M,N] = sum_k A[m,k]*B[n,k] (both K-major). ONE pass per GEMM.
// MODE 0: A=Ut, B=q.   epi: v*dq_mul - dq_sub*colsum[row] -> T1 (fp16)
// MODE 1: A=T1, B=Vt.  epi: v / scaleWH[col]              -> W  (fp16)
// MODE 2: A=x,  B=W.   epi: v + bias[col]                 -> out (fp32)
// NEW: CTA tile 128x128 (warp tile 64x32), <=128 regs, 2 CTAs/SM for cross-CTA overlap.
constexpr int BM = 128, BN = 128, BK = 64, NCHUNK = KDIM / BK;
constexpr uint32_t TILE_A = 128 * 128;   // 16 KB
constexpr uint32_t TILE_B = 128 * 128;   // 16 KB
constexpr uint32_t OFF_A = 0, OFF_B = TILE_A;
constexpr uint32_t ST = TILE_A + TILE_B;           // 32 KB per stage
constexpr uint32_t SMEM_SZ = 2 * ST + 1024;        // 65 KB -> two CTAs fit
constexpr int WM = 64, WN = 32, MT = WM / 16, NT = WN / 8;

template <int MODE>
__global__ __launch_bounds__(256, 2) void hgemm(const float* __restrict__ aux,
                                                float* __restrict__ outp) {
    const fp16 *A, *B;
    if (MODE == 0) { A = g_Ut; B = g_qf; }
    if (MODE == 1) { A = g_T1; B = g_Vt; }
    if (MODE == 2) { A = g_x;  B = g_W; }

    extern __shared__ char dsm[];
    const uint32_t sbase = (smem_u32(dsm) + 1023u) & ~1023u;

    const int tid = threadIdx.x;
    const int wid = tid >> 5, lane = tid & 31;
    const int warp_m = wid >> 2;   // 0..1  (64 rows)
    const int warp_n = wid & 3;    // 0..3  (32 cols)
    const int m0 = blockIdx.y * BM, n0 = blockIdx.x * BN;

    float acc[MT][NT][4];
#pragma unroll
    for (int a = 0; a < MT; a++)
#pragma unroll
        for (int b = 0; b < NT; b++)
#pragma unroll
            for (int d = 0; d < 4; d++) acc[a][b][d] = 0.f;

    auto load_stage = [&](int s, int c) {
        const uint32_t sb = sbase + (uint32_t)s * ST;
        const int k0 = c * BK;
#pragma unroll
        for (int t = 0; t < 4; t++) {          // A: 1024 slots
            int idx = tid + t * 256;
            int r = idx >> 3, cc = idx & 7;
            uint32_t sw = sw128((uint32_t)(r * 128 + cc * 16));
            cp16(sb + OFF_A + sw, A + (size_t)(m0 + r) * KDIM + k0 + cc * 8);
        }
#pragma unroll
        for (int t = 0; t < 4; t++) {          // B: 1024 slots
            int idx = tid + t * 256;
            int r = idx >> 3, cc = idx & 7;
            uint32_t sw = sw128((uint32_t)(r * 128 + cc * 16));
            cp16(sb + OFF_B + sw, B + (size_t)(n0 + r) * KDIM + k0 + cc * 8);
        }
        asm volatile("cp.async.commit_group;");
    };

    load_stage(0, 0);

    const uint32_t a_row = (uint32_t)(warp_m * WM + (lane & 15));
    const uint32_t a_kb  = (uint32_t)((lane >> 4) << 4);
    const uint32_t b_row = (uint32_t)(warp_n * WN + ((lane >> 4) << 3) + (lane & 7));
    const uint32_t b_kb  = (uint32_t)(((lane >> 3) & 1) << 4);

    for (int c = 0; c < NCHUNK; c++) {
        asm volatile("cp.async.wait_group 0;");
        __syncthreads();
        if (c + 1 < NCHUNK) load_stage((c + 1) & 1, c + 1);

        const uint32_t sb = sbase + (uint32_t)(c & 1) * ST;
#pragma unroll
        for (int ks = 0; ks < BK / 16; ks++) {
            uint32_t ar[MT][4], br[NT][2];
#pragma unroll
            for (int mt = 0; mt < MT; mt++) {
                uint32_t o = sw128((a_row + mt * 16) * 128 + ks * 32 + a_kb);
                ldsm4(ar[mt], sb + OFF_A + o);
            }
#pragma unroll
            for (int np = 0; np < NT / 2; np++) {
                uint32_t o = sw128((b_row + np * 16) * 128 + ks * 32 + b_kb);
                uint32_t tmp[4];
                ldsm4(tmp, sb + OFF_B + o);
                br[2 * np][0] = tmp[0]; br[2 * np][1] = tmp[1];
                br[2 * np + 1][0] = tmp[2]; br[2 * np + 1][1] = tmp[3];
            }
#pragma unroll
            for (int mt = 0; mt < MT; mt++)
#pragma unroll
                for (int nt = 0; nt < NT; nt++)
                    mma16816(acc[mt][nt], ar[mt], br[nt]);
        }
    }

    // ---------------- epilogue ----------------
    const int gid = lane >> 2, tig = lane & 3;
    float dq_mul = 0.f, dq_sub = 0.f;
    if (MODE == 0) { float sc = aux[0]; dq_mul = sc * (2.0f / 15.0f); dq_sub = sc; }

    float c0f[NT], c1f[NT];
#pragma unroll
    for (int nt = 0; nt < NT; nt++) {
        int col = n0 + warp_n * WN + nt * 8 + tig * 2;
        if (MODE == 1) { c0f[nt] = 1.0f / aux[col]; c1f[nt] = 1.0f / aux[col + 1]; }
        else if (MODE == 2) { c0f[nt] = aux[col]; c1f[nt] = aux[col + 1]; }
        else { c0f[nt] = 0.f; c1f[nt] = 0.f; }
    }

#pragma unroll
    for (int mt = 0; mt < MT; mt++) {
        int r0 = m0 + warp_m * WM + mt * 16 + gid;
        int r1 = r0 + 8;
        float sub0 = 0.f, sub1 = 0.f;
        if (MODE == 0) {
            float cs0 = 0.f, cs1 = 0.f;
#pragma unroll
            for (int p = 0; p < 8; p++) {
                cs0 += g_cs_part[p * 4096 + r0];
                cs1 += g_cs_part[p * 4096 + r1];
            }
            sub0 = dq_sub * cs0; sub1 = dq_sub * cs1;
        }
#pragma unroll
        for (int nt = 0; nt < NT; nt++) {
            int col = n0 + warp_n * WN + nt * 8 + tig * 2;
            float v0 = acc[mt][nt][0], v1 = acc[mt][nt][1];
            float v2 = acc[mt][nt][2], v3 = acc[mt][nt][3];
            if (MODE == 0) {
                v0 = v0 * dq_mul - sub0; v1 = v1 * dq_mul - sub0;
                v2 = v2 * dq_mul - sub1; v3 = v3 * dq_mul - sub1;
            } else if (MODE == 1) {
                v0 *= c0f[nt]; v1 *= c1f[nt]; v2 *= c0f[nt]; v3 *= c1f[nt];
            } else {
                v0 += c0f[nt]; v1 += c1f[nt]; v2 += c0f[nt]; v3 += c1f[nt];
            }
            if (MODE == 2) {
                *(float2*)(outp + (size_t)r0 * 4096 + col) = make_float2(v0, v1);
                *(float2*)(outp + (size_t)r1 * 4096 + col) = make_float2(v2, v3);
            } else {
                fp16* C = (MODE == 0) ? g_T1 : g_W;
                union { fp16 b[2]; uint32_t u; } h;
                h.b[0] = __float2half_rn(v0); h.b[1] = __float2half_rn(v1);
                *(uint32_t*)(C + (size_t)r0 * 4096 + col) = h.u;
                h.b[0] = __float2half_rn(v2); h.b[1] = __float2half_rn(v3);
                *(uint32_t*)(C + (size_t)r1 * 4096 + col) = h.u;
            }
        }
    }
}

// ---------------- host ----------------
extern "C" void kernel_launch(void* const* d_in, const int* in_sizes, int n_in,
                              void* d_out, int out_size) {
    const float* x       = (const float*)d_in[0];
    const int*   qweight = (const int*)  d_in[1];
    const float* scale   = (const float*)d_in[2];
    const float* scaleWH = (const float*)d_in[3];
    const float* bias    = (const float*)d_in[4];
    const float* U       = (const float*)d_in[5];
    const float* V       = (const float*)d_in[6];
    float*       out     = (float*)d_out;

    cudaFuncSetAttribute(hgemm<0>, cudaFuncAttributeMaxDynamicSharedMemorySize, SMEM_SZ);
    cudaFuncSetAttribute(hgemm<1>, cudaFuncAttributeMaxDynamicSharedMemorySize, SMEM_SZ);
    cudaFuncSetAttribute(hgemm<2>, cudaFuncAttributeMaxDynamicSharedMemorySize, SMEM_SZ);

    dim3 tb32(32, 8);
    colsum_part<<<dim3(16, 8), 256>>>(U);                         // 0
    transconv<0><<<dim3(128, 128), tb32>>>(U);                    // 1
    convq<<<16384, 256>>>(qweight);                               // 2
    hgemm<0><<<dim3(32, 32), 256, SMEM_SZ>>>(scale, nullptr);     // 3 <- profiled
    transconv<1><<<dim3(128, 128), tb32>>>(V);                    // 4
    hgemm<1><<<dim3(32, 32), 256, SMEM_SZ>>>(scaleWH, nullptr);   // 5
    convx<<<(unsigned)(SZ_X / 4 / 256), 256>>>(x);                // 6
    hgemm<2><<<dim3(32, 64), 256, SMEM_SZ>>>(bias, out);          // 7
}